// round 1
// baseline (speedup 1.0000x reference)
#include <cuda_runtime.h>
#include <math.h>

#define S_LEN 4096
#define LCC   16
#define CH    128      // char hidden
#define CD    64       // char emb dim
#define CG    512      // 4*CH
#define CK    192      // CD+CH
#define ND    256      // word emb dim
#define NH    512      // word hidden
#define NG    2048     // 4*NH
#define NK    384      // ND+CH
#define NTAG  64
#define NBW   64       // persistent word-rec blocks
#define HPER  8        // NH/NBW

// ---- scratch (no allocs allowed; __device__ globals) ----
__device__ float    g_charH[S_LEN * CH];     // 2 MB
__device__ float    g_charC[S_LEN * CH];     // 2 MB
__device__ float    g_gin  [S_LEN * NG];     // 32 MB : word input projection
__device__ float    g_hs   [S_LEN * NH];     // 8 MB  : word LSTM hidden states
__device__ unsigned g_bar;                   // persistent-kernel barrier counter

__device__ __forceinline__ float sigf(float x) { return 1.0f / (1.0f + expf(-x)); }

// ============================================================================
// Char LSTM: one launch per timestep t. Block = 32 words, computes all 512
// gates (K=192 fused [emb | h] @ [Wih | Whh].T), then masked c/h update.
// ============================================================================
__global__ void __launch_bounds__(256, 1)
char_step_kernel(const float* __restrict__ char_emb,
                 const float* __restrict__ cWih,
                 const float* __restrict__ cWhh,
                 const float* __restrict__ cbih,
                 const float* __restrict__ cbhh,
                 const int*   __restrict__ chars,
                 const int*   __restrict__ char_lens,
                 int t)
{
    extern __shared__ float sm[];
    float* feat = sm;                    // [32][CK]
    float* wsm  = feat + 32 * CK;        // [128][CK+1]  (pad for bank-conflict-free)
    float* gbuf = wsm + 128 * (CK + 1);  // [32][CG]
    const int tid = threadIdx.x;
    const int s0  = blockIdx.x * 32;

    // build feature tile: [emb(64) | h_prev(128)]
    for (int i = tid; i < 32 * CK; i += 256) {
        int w = i / CK, k = i - w * CK;
        int s = s0 + w;
        float v;
        if (k < CD) v = char_emb[chars[s * LCC + t] * CD + k];
        else        v = g_charH[s * CH + (k - CD)];
        feat[w * CK + k] = v;
    }
    __syncthreads();

    const int tx = tid & 31, ty = tid >> 5;
    for (int gc = 0; gc < 4; gc++) {               // 4 chunks of 128 gates
        for (int i = tid; i < 128 * CK; i += 256) {
            int r = i / CK, k = i - r * CK;
            int G = gc * 128 + r;
            float v = (k < CD) ? cWih[G * CD + k] : cWhh[G * CH + (k - CD)];
            wsm[r * (CK + 1) + k] = v;
        }
        __syncthreads();

        float acc[4][4] = {};                      // 4 words x 4 gates per thread
        #pragma unroll 4
        for (int k = 0; k < CK; k++) {
            float b0 = wsm[(tx     ) * (CK + 1) + k];
            float b1 = wsm[(tx + 32) * (CK + 1) + k];
            float b2 = wsm[(tx + 64) * (CK + 1) + k];
            float b3 = wsm[(tx + 96) * (CK + 1) + k];
            #pragma unroll
            for (int i = 0; i < 4; i++) {
                float a = feat[(ty + 8 * i) * CK + k];
                acc[i][0] = fmaf(a, b0, acc[i][0]);
                acc[i][1] = fmaf(a, b1, acc[i][1]);
                acc[i][2] = fmaf(a, b2, acc[i][2]);
                acc[i][3] = fmaf(a, b3, acc[i][3]);
            }
        }
        #pragma unroll
        for (int j = 0; j < 4; j++) {
            int g = gc * 128 + tx + 32 * j;
            float bsum = cbih[g] + cbhh[g];
            #pragma unroll
            for (int i = 0; i < 4; i++)
                gbuf[(ty + 8 * i) * CG + g] = acc[i][j] + bsum;
        }
        __syncthreads();
    }

    // masked LSTM cell update
    for (int i = tid; i < 32 * CH; i += 256) {
        int w = i >> 7, hh = i & 127;
        int s = s0 + w;
        float gi = gbuf[w * CG + hh];
        float gf = gbuf[w * CG + CH + hh];
        float gg = gbuf[w * CG + 2 * CH + hh];
        float go = gbuf[w * CG + 3 * CH + hh];
        float cprev = g_charC[s * CH + hh];
        float hprev = g_charH[s * CH + hh];
        float cn = sigf(gf) * cprev + sigf(gi) * tanhf(gg);
        float hn = sigf(go) * tanhf(cn);
        bool m = (t < char_lens[s]);
        g_charC[s * CH + hh] = m ? cn : cprev;
        g_charH[s * CH + hh] = m ? hn : hprev;
    }
}

// ============================================================================
// Word LSTM input projection: g_gin = [word_emb[x] | char_h] @ Wih.T + bih+bhh
// GEMM M=4096 N=2048 K=384; block tile 32 words x 128 gates.
// ============================================================================
__global__ void __launch_bounds__(256, 1)
word_gin_kernel(const float* __restrict__ word_emb,
                const float* __restrict__ Wih,
                const float* __restrict__ bih,
                const float* __restrict__ bhh,
                const int*   __restrict__ x)
{
    extern __shared__ float sm[];
    float* feat = sm;              // [32][NK]
    float* wc   = feat + 32 * NK;  // [128][33]
    const int tid = threadIdx.x;
    const int s0  = blockIdx.x * 32;
    const int g0  = blockIdx.y * 128;

    for (int i = tid; i < 32 * NK; i += 256) {
        int w = i / NK, k = i - w * NK;
        int s = s0 + w;
        float v;
        if (k < ND) v = word_emb[x[s] * ND + k];
        else        v = g_charH[s * CH + (k - ND)];
        feat[w * NK + k] = v;
    }
    __syncthreads();

    const int tx = tid & 31, ty = tid >> 5;
    float acc[4][4] = {};
    for (int kc = 0; kc < NK; kc += 32) {
        for (int i = tid; i < 128 * 32; i += 256) {
            int r = i >> 5, k = i & 31;
            wc[r * 33 + k] = Wih[(g0 + r) * NK + kc + k];
        }
        __syncthreads();
        #pragma unroll 4
        for (int k = 0; k < 32; k++) {
            float b0 = wc[(tx     ) * 33 + k];
            float b1 = wc[(tx + 32) * 33 + k];
            float b2 = wc[(tx + 64) * 33 + k];
            float b3 = wc[(tx + 96) * 33 + k];
            #pragma unroll
            for (int i = 0; i < 4; i++) {
                float a = feat[(ty + 8 * i) * NK + kc + k];
                acc[i][0] = fmaf(a, b0, acc[i][0]);
                acc[i][1] = fmaf(a, b1, acc[i][1]);
                acc[i][2] = fmaf(a, b2, acc[i][2]);
                acc[i][3] = fmaf(a, b3, acc[i][3]);
            }
        }
        __syncthreads();
    }
    #pragma unroll
    for (int j = 0; j < 4; j++) {
        int g = g0 + tx + 32 * j;
        float bsum = bih[g] + bhh[g];
        #pragma unroll
        for (int i = 0; i < 4; i++)
            g_gin[(s0 + ty + 8 * i) * NG + g] = acc[i][j] + bsum;
    }
}

// ============================================================================
// Word LSTM recurrence: persistent kernel, 64 resident CTAs, 4096 sequential
// steps. CTA b owns h-indices [8b, 8b+8) => 32 gate rows; Whh slice lives in
// REGISTERS (64 fp32/thread). h broadcast through L2 with .cg, custom
// atomic-counter barrier per step. Cell state c never leaves the SM.
// ============================================================================
__global__ void __launch_bounds__(256, 1)
word_rec_kernel(const float* __restrict__ Whh)
{
    __shared__ float hsm[NH];
    __shared__ float part[256];
    __shared__ float gates[32];
    const int tid = threadIdx.x;
    const int r   = tid & 31;       // gate row within block (q*8 + hl)
    const int sub = tid >> 5;       // k-slice: k = sub*64 .. +63
    const int G   = (r >> 3) * NH + blockIdx.x * HPER + (r & 7);  // global gate row

    float W[64];
    #pragma unroll
    for (int j = 0; j < 64; j++) W[j] = Whh[G * NH + sub * 64 + j];

    float c = 0.0f;                           // cell state (threads 0..7 only)
    volatile unsigned* barp = &g_bar;

    for (int t = 0; t < S_LEN; t++) {
        // prefetch this step's input-projection term (independent of barrier)
        float ginv = (sub == 0) ? g_gin[t * NG + G] : 0.0f;

        if (t > 0) {
            if (tid == 0) {
                unsigned tgt = (unsigned)t * NBW;
                while (*barp < tgt) { }       // spin on L2 (volatile bypasses L1)
            }
            __syncthreads();
            hsm[tid]       = __ldcg(&g_hs[(t - 1) * NH + tid]);
            hsm[tid + 256] = __ldcg(&g_hs[(t - 1) * NH + tid + 256]);
        } else {
            hsm[tid] = 0.0f;
            hsm[tid + 256] = 0.0f;
        }
        __syncthreads();

        float p = 0.0f;
        #pragma unroll
        for (int j = 0; j < 64; j++) p = fmaf(W[j], hsm[sub * 64 + j], p);
        part[sub * 32 + r] = p;
        __syncthreads();

        if (tid < 32) {
            float g = ginv;
            #pragma unroll
            for (int sb = 0; sb < 8; sb++) g += part[sb * 32 + tid];
            gates[tid] = g;
            __syncwarp();
            if (tid < 8) {
                float gi = gates[tid], gf = gates[8 + tid];
                float gg = gates[16 + tid], go = gates[24 + tid];
                float cn = sigf(gf) * c + sigf(gi) * tanhf(gg);
                c = cn;
                float hn = sigf(go) * tanhf(cn);
                __stcg(&g_hs[t * NH + blockIdx.x * HPER + tid], hn);
                __threadfence();              // publish h before the release-add
            }
        }
        __syncthreads();
        if (tid == 0) atomicAdd(&g_bar, 1u);
    }
}

// ============================================================================
// Logits + log_softmax: out[s,:] = log_softmax(hs[s] @ W1.T + b1)
// Block = 32 words; full W1 (64x512) in SMEM.
// ============================================================================
__global__ void __launch_bounds__(256, 1)
logits_kernel(const float* __restrict__ W1,
              const float* __restrict__ b1,
              float* __restrict__ out)
{
    extern __shared__ float sm[];
    float* w1s = sm;                 // [64][513]
    float* hsm = w1s + 64 * 513;     // [32][512]
    float* lsm = hsm + 32 * 512;     // [32][64]
    const int tid = threadIdx.x;
    const int s0  = blockIdx.x * 32;

    for (int i = tid; i < 64 * 512; i += 256) {
        int rr = i >> 9, k = i & 511;
        w1s[rr * 513 + k] = W1[i];
    }
    for (int i = tid; i < 32 * 512; i += 256)
        hsm[i] = g_hs[s0 * 512 + i];
    __syncthreads();

    const int tg = tid & 63, wg = tid >> 6;     // tag, word-group
    float acc[8];
    #pragma unroll
    for (int i = 0; i < 8; i++) acc[i] = b1[tg];
    #pragma unroll 4
    for (int k = 0; k < 512; k++) {
        float b = w1s[tg * 513 + k];
        #pragma unroll
        for (int i = 0; i < 8; i++)
            acc[i] = fmaf(hsm[(wg + 4 * i) * 512 + k], b, acc[i]);
    }
    #pragma unroll
    for (int i = 0; i < 8; i++)
        lsm[(wg + 4 * i) * 64 + tg] = acc[i];
    __syncthreads();

    // log_softmax: each warp handles 4 words, 2 tags/lane
    const int lane = tid & 31, wrp = tid >> 5;
    for (int wi = 0; wi < 4; wi++) {
        int w = wrp * 4 + wi;
        float v0 = lsm[w * 64 + lane];
        float v1 = lsm[w * 64 + 32 + lane];
        float m = fmaxf(v0, v1);
        #pragma unroll
        for (int o = 16; o > 0; o >>= 1) m = fmaxf(m, __shfl_xor_sync(0xffffffffu, m, o));
        float se = expf(v0 - m) + expf(v1 - m);
        #pragma unroll
        for (int o = 16; o > 0; o >>= 1) se += __shfl_xor_sync(0xffffffffu, se, o);
        float ls = m + logf(se);
        out[(s0 + w) * 64 + lane]      = v0 - ls;
        out[(s0 + w) * 64 + 32 + lane] = v1 - ls;
    }
}

// ============================================================================
extern "C" void kernel_launch(void* const* d_in, const int* in_sizes, int n_in,
                              void* d_out, int out_size)
{
    const float* char_emb  = (const float*)d_in[0];
    const float* cWih      = (const float*)d_in[1];
    const float* cWhh      = (const float*)d_in[2];
    const float* cbih      = (const float*)d_in[3];
    const float* cbhh      = (const float*)d_in[4];
    const float* word_emb  = (const float*)d_in[5];
    const float* Wih       = (const float*)d_in[6];
    const float* Whh       = (const float*)d_in[7];
    const float* bih       = (const float*)d_in[8];
    const float* bhh       = (const float*)d_in[9];
    const float* W1        = (const float*)d_in[10];
    const float* b1        = (const float*)d_in[11];
    const int*   x         = (const int*)d_in[12];
    const int*   chars     = (const int*)d_in[13];
    const int*   char_lens = (const int*)d_in[14];
    float* out = (float*)d_out;
    (void)in_sizes; (void)n_in; (void)out_size;

    void *pH, *pC, *pBar;
    cudaGetSymbolAddress(&pH, g_charH);
    cudaGetSymbolAddress(&pC, g_charC);
    cudaGetSymbolAddress(&pBar, g_bar);
    cudaMemsetAsync(pH, 0, sizeof(float) * S_LEN * CH, 0);
    cudaMemsetAsync(pC, 0, sizeof(float) * S_LEN * CH, 0);
    cudaMemsetAsync(pBar, 0, sizeof(unsigned), 0);

    const size_t sm_char = sizeof(float) * (32 * CK + 128 * (CK + 1) + 32 * CG);
    const size_t sm_gin  = sizeof(float) * (32 * NK + 128 * 33);
    const size_t sm_log  = sizeof(float) * (64 * 513 + 32 * 512 + 32 * 64);
    cudaFuncSetAttribute(char_step_kernel, cudaFuncAttributeMaxDynamicSharedMemorySize, (int)sm_char);
    cudaFuncSetAttribute(word_gin_kernel,  cudaFuncAttributeMaxDynamicSharedMemorySize, (int)sm_gin);
    cudaFuncSetAttribute(logits_kernel,    cudaFuncAttributeMaxDynamicSharedMemorySize, (int)sm_log);

    for (int t = 0; t < LCC; t++)
        char_step_kernel<<<S_LEN / 32, 256, sm_char>>>(char_emb, cWih, cWhh,
                                                       cbih, cbhh, chars, char_lens, t);

    dim3 ggrid(S_LEN / 32, NG / 128);
    word_gin_kernel<<<ggrid, 256, sm_gin>>>(word_emb, Wih, bih, bhh, x);

    word_rec_kernel<<<NBW, 256>>>(Whh);

    logits_kernel<<<S_LEN / 32, 256, sm_log>>>(W1, b1, out);
}

// round 3
// speedup vs baseline: 1.2962x; 1.2962x over previous
#include <cuda_runtime.h>
#include <math.h>

#define S_LEN 4096
#define LCC   16
#define CH    128      // char hidden
#define CD    64       // char emb dim
#define CG    512      // 4*CH
#define CK    192      // CD+CH
#define ND    256      // word emb dim
#define NH    512      // word hidden
#define NG    2048     // 4*NH
#define NK    384      // ND+CH
#define NTAG  64
#define NBW   64       // persistent word-rec blocks
#define HPER  8        // NH/NBW

// ---- scratch (__device__ globals; no allocs allowed) ----
__device__ float              g_charH[S_LEN * CH];   // final char-LSTM h
__device__ float              g_gin  [S_LEN * NG];   // word input projection
__device__ float              g_hs   [S_LEN * NH];   // word LSTM hidden states
__device__ unsigned long long g_hrec [2 * NH];       // tagged h records (double buffer)

__device__ __forceinline__ float sigf(float x)  { return 1.0f / (1.0f + __expf(-x)); }
__device__ __forceinline__ float tanhf_fast(float x) { return 2.0f / (1.0f + __expf(-2.0f * x)) - 1.0f; }

// ============================================================================
// Char LSTM: ONE launch, 128 CTAs x 32 words, internal loop over t=0..15.
// c lives in registers, h in SMEM. Gate chunk == gate type -> cell update in
// registers, no gate buffer. Weights streamed from L2 each (t, chunk).
// ============================================================================
__global__ void __launch_bounds__(256)
char_lstm_kernel(const float* __restrict__ char_emb,
                 const float* __restrict__ cWih,
                 const float* __restrict__ cWhh,
                 const float* __restrict__ cbih,
                 const float* __restrict__ cbhh,
                 const int*   __restrict__ chars,
                 const int*   __restrict__ char_lens)
{
    extern __shared__ float sm[];
    float* wsm  = sm;                       // [128][193]
    float* esm  = wsm + 128 * 193;          // [32][64]
    float* hsm  = esm + 32 * 64;            // [32][128]
    int*   cidx = (int*)(hsm + 32 * CH);    // [32][16]

    const int tid = threadIdx.x;
    const int s0  = blockIdx.x * 32;
    const int tx  = tid & 31, ty = tid >> 5;

    // cache char ids for all 16 steps (512 entries -> grid-stride, BUGFIX)
    for (int i = tid; i < 32 * LCC; i += 256) cidx[i] = chars[s0 * LCC + i];
    // zero h
    for (int i = tid; i < 32 * CH; i += 256) hsm[i] = 0.0f;

    // per-thread state: words w = ty+8i (i<4), h-idx hh = tx+32j (j<4)
    float c[4][4];
    #pragma unroll
    for (int i = 0; i < 4; i++)
        #pragma unroll
        for (int j = 0; j < 4; j++) c[i][j] = 0.0f;

    int len[4];
    #pragma unroll
    for (int i = 0; i < 4; i++) len[i] = char_lens[s0 + ty + 8 * i];

    float bsum[4][4];
    #pragma unroll
    for (int gc = 0; gc < 4; gc++)
        #pragma unroll
        for (int j = 0; j < 4; j++) {
            int G = gc * 128 + tx + 32 * j;
            bsum[gc][j] = cbih[G] + cbhh[G];
        }
    __syncthreads();

    for (int t = 0; t < LCC; t++) {
        // fill embedding tile
        for (int i = tid; i < 32 * CD; i += 256) {
            int w = i >> 6, k = i & 63;
            esm[i] = char_emb[cidx[w * LCC + t] * CD + k];
        }
        __syncthreads();

        float a4[4][4][4];   // [word][hh][gate]
        #pragma unroll
        for (int gc = 0; gc < 4; gc++) {
            // stage 128 gate rows (= one gate type), K=192 fused [Wih|Whh]
            for (int i = tid; i < 128 * CK; i += 256) {
                int rr = i / CK, k = i - rr * CK;
                int G = gc * 128 + rr;
                float v = (k < CD) ? cWih[G * CD + k] : cWhh[G * CH + (k - CD)];
                wsm[rr * 193 + k] = v;
            }
            __syncthreads();

            float acc[4][4] = {};
            // emb part
            #pragma unroll 4
            for (int k = 0; k < CD; k++) {
                float b0 = wsm[(tx     ) * 193 + k];
                float b1 = wsm[(tx + 32) * 193 + k];
                float b2 = wsm[(tx + 64) * 193 + k];
                float b3 = wsm[(tx + 96) * 193 + k];
                #pragma unroll
                for (int i = 0; i < 4; i++) {
                    float a = esm[(ty + 8 * i) * CD + k];
                    acc[i][0] = fmaf(a, b0, acc[i][0]);
                    acc[i][1] = fmaf(a, b1, acc[i][1]);
                    acc[i][2] = fmaf(a, b2, acc[i][2]);
                    acc[i][3] = fmaf(a, b3, acc[i][3]);
                }
            }
            // h part
            #pragma unroll 4
            for (int k = 0; k < CH; k++) {
                float b0 = wsm[(tx     ) * 193 + CD + k];
                float b1 = wsm[(tx + 32) * 193 + CD + k];
                float b2 = wsm[(tx + 64) * 193 + CD + k];
                float b3 = wsm[(tx + 96) * 193 + CD + k];
                #pragma unroll
                for (int i = 0; i < 4; i++) {
                    float a = hsm[(ty + 8 * i) * CH + k];
                    acc[i][0] = fmaf(a, b0, acc[i][0]);
                    acc[i][1] = fmaf(a, b1, acc[i][1]);
                    acc[i][2] = fmaf(a, b2, acc[i][2]);
                    acc[i][3] = fmaf(a, b3, acc[i][3]);
                }
            }
            #pragma unroll
            for (int i = 0; i < 4; i++)
                #pragma unroll
                for (int j = 0; j < 4; j++)
                    a4[i][j][gc] = acc[i][j] + bsum[gc][j];
            __syncthreads();
        }

        // cell update in registers; masked h write to SMEM
        #pragma unroll
        for (int i = 0; i < 4; i++) {
            bool m = (t < len[i]);
            int w = ty + 8 * i;
            #pragma unroll
            for (int j = 0; j < 4; j++) {
                float gi = a4[i][j][0], gf = a4[i][j][1];
                float gg = a4[i][j][2], go = a4[i][j][3];
                float cn = sigf(gf) * c[i][j] + sigf(gi) * tanhf_fast(gg);
                float hn = sigf(go) * tanhf_fast(cn);
                if (m) {
                    c[i][j] = cn;
                    hsm[w * CH + tx + 32 * j] = hn;
                }
            }
        }
        __syncthreads();
    }

    // publish final h
    for (int i = tid; i < 32 * CH; i += 256)
        g_charH[s0 * CH + i] = hsm[i];
}

// ============================================================================
// Word LSTM input projection: g_gin = [word_emb[x] | char_h] @ Wih.T + bih+bhh
// ============================================================================
__global__ void __launch_bounds__(256)
word_gin_kernel(const float* __restrict__ word_emb,
                const float* __restrict__ Wih,
                const float* __restrict__ bih,
                const float* __restrict__ bhh,
                const int*   __restrict__ x)
{
    extern __shared__ float sm[];
    float* feat = sm;              // [32][NK]
    float* wc   = feat + 32 * NK;  // [128][33]
    const int tid = threadIdx.x;
    const int s0  = blockIdx.x * 32;
    const int g0  = blockIdx.y * 128;

    for (int i = tid; i < 32 * NK; i += 256) {
        int w = i / NK, k = i - w * NK;
        int s = s0 + w;
        float v;
        if (k < ND) v = word_emb[x[s] * ND + k];
        else        v = g_charH[s * CH + (k - ND)];
        feat[w * NK + k] = v;
    }
    __syncthreads();

    const int tx = tid & 31, ty = tid >> 5;
    float acc[4][4] = {};
    for (int kc = 0; kc < NK; kc += 32) {
        for (int i = tid; i < 128 * 32; i += 256) {
            int r = i >> 5, k = i & 31;
            wc[r * 33 + k] = Wih[(g0 + r) * NK + kc + k];
        }
        __syncthreads();
        #pragma unroll 4
        for (int k = 0; k < 32; k++) {
            float b0 = wc[(tx     ) * 33 + k];
            float b1 = wc[(tx + 32) * 33 + k];
            float b2 = wc[(tx + 64) * 33 + k];
            float b3 = wc[(tx + 96) * 33 + k];
            #pragma unroll
            for (int i = 0; i < 4; i++) {
                float a = feat[(ty + 8 * i) * NK + kc + k];
                acc[i][0] = fmaf(a, b0, acc[i][0]);
                acc[i][1] = fmaf(a, b1, acc[i][1]);
                acc[i][2] = fmaf(a, b2, acc[i][2]);
                acc[i][3] = fmaf(a, b3, acc[i][3]);
            }
        }
        __syncthreads();
    }
    #pragma unroll
    for (int j = 0; j < 4; j++) {
        int g = g0 + tx + 32 * j;
        float bsum = bih[g] + bhh[g];
        #pragma unroll
        for (int i = 0; i < 4; i++)
            g_gin[(s0 + ty + 8 * i) * NG + g] = acc[i][j] + bsum;
    }
}

// ============================================================================
// Word LSTM recurrence: 64 persistent CTAs, 4096 steps. Sync via tagged
// 64-bit records {tag=t+1 | float h}: single-copy-atomic store, poll IS the
// data read -> ONE L2 round trip per step. Double-buffered by step parity.
// ============================================================================
__global__ void __launch_bounds__(256)
word_rec_kernel(const float* __restrict__ Whh)
{
    __shared__ float hsm[NH];
    __shared__ float part[256];
    __shared__ float gates[32];
    const int tid = threadIdx.x;
    const int r   = tid & 31;       // gate row within block
    const int sub = tid >> 5;       // k-slice
    const int G   = (r >> 3) * NH + blockIdx.x * HPER + (r & 7);

    float W[64];
    #pragma unroll
    for (int j = 0; j < 64; j++) W[j] = Whh[G * NH + sub * 64 + j];

    float c = 0.0f;
    const int r0 = 2 * tid, r1 = 2 * tid + 1;

    for (int t = 0; t < S_LEN; t++) {
        // prefetch input-projection term (tid<32 <=> sub==0 holds the gates)
        float ginv = (sub == 0) ? __ldg(&g_gin[t * NG + G]) : 0.0f;

        if (t > 0) {
            const unsigned tag = (unsigned)t;  // h(t-1) carries tag t
            const volatile unsigned long long* rec = g_hrec + ((t - 1) & 1) * NH;
            unsigned long long v0 = rec[r0];
            unsigned long long v1 = rec[r1];
            while ((unsigned)(v0 >> 32) != tag) v0 = rec[r0];
            hsm[r0] = __uint_as_float((unsigned)v0);
            while ((unsigned)(v1 >> 32) != tag) v1 = rec[r1];
            hsm[r1] = __uint_as_float((unsigned)v1);
        } else {
            hsm[tid] = 0.0f;
            hsm[tid + 256] = 0.0f;
        }
        __syncthreads();

        float p = 0.0f;
        #pragma unroll
        for (int j = 0; j < 64; j++) p = fmaf(W[j], hsm[sub * 64 + j], p);
        part[sub * 32 + r] = p;
        __syncthreads();

        if (tid < 32) {
            float g = ginv;
            #pragma unroll
            for (int sb = 0; sb < 8; sb++) g += part[sb * 32 + tid];
            gates[tid] = g;
            __syncwarp();
            if (tid < 8) {
                float gi = gates[tid], gf = gates[8 + tid];
                float gg = gates[16 + tid], go = gates[24 + tid];
                float cn = sigf(gf) * c + sigf(gi) * tanhf_fast(gg);
                c = cn;
                float hn = sigf(go) * tanhf_fast(cn);
                int hidx = blockIdx.x * HPER + tid;
                g_hs[t * NH + hidx] = hn;
                unsigned long long pk =
                    ((unsigned long long)(unsigned)(t + 1) << 32) | __float_as_uint(hn);
                *(volatile unsigned long long*)(g_hrec + (t & 1) * NH + hidx) = pk;
            }
        }
    }
}

// ============================================================================
// Logits + log_softmax
// ============================================================================
__global__ void __launch_bounds__(256)
logits_kernel(const float* __restrict__ W1,
              const float* __restrict__ b1,
              float* __restrict__ out)
{
    extern __shared__ float sm[];
    float* w1s = sm;                 // [64][513]
    float* hsm = w1s + 64 * 513;     // [32][512]
    float* lsm = hsm + 32 * 512;     // [32][64]
    const int tid = threadIdx.x;
    const int s0  = blockIdx.x * 32;

    for (int i = tid; i < 64 * 512; i += 256) {
        int rr = i >> 9, k = i & 511;
        w1s[rr * 513 + k] = W1[i];
    }
    for (int i = tid; i < 32 * 512; i += 256)
        hsm[i] = g_hs[s0 * 512 + i];
    __syncthreads();

    const int tg = tid & 63, wg = tid >> 6;
    float acc[8];
    #pragma unroll
    for (int i = 0; i < 8; i++) acc[i] = b1[tg];
    #pragma unroll 4
    for (int k = 0; k < 512; k++) {
        float b = w1s[tg * 513 + k];
        #pragma unroll
        for (int i = 0; i < 8; i++)
            acc[i] = fmaf(hsm[(wg + 4 * i) * 512 + k], b, acc[i]);
    }
    #pragma unroll
    for (int i = 0; i < 8; i++)
        lsm[(wg + 4 * i) * 64 + tg] = acc[i];
    __syncthreads();

    const int lane = tid & 31, wrp = tid >> 5;
    for (int wi = 0; wi < 4; wi++) {
        int w = wrp * 4 + wi;
        float v0 = lsm[w * 64 + lane];
        float v1 = lsm[w * 64 + 32 + lane];
        float m = fmaxf(v0, v1);
        #pragma unroll
        for (int o = 16; o > 0; o >>= 1) m = fmaxf(m, __shfl_xor_sync(0xffffffffu, m, o));
        float se = expf(v0 - m) + expf(v1 - m);
        #pragma unroll
        for (int o = 16; o > 0; o >>= 1) se += __shfl_xor_sync(0xffffffffu, se, o);
        float ls = m + logf(se);
        out[(s0 + w) * 64 + lane]      = v0 - ls;
        out[(s0 + w) * 64 + 32 + lane] = v1 - ls;
    }
}

// ============================================================================
extern "C" void kernel_launch(void* const* d_in, const int* in_sizes, int n_in,
                              void* d_out, int out_size)
{
    const float* char_emb  = (const float*)d_in[0];
    const float* cWih      = (const float*)d_in[1];
    const float* cWhh      = (const float*)d_in[2];
    const float* cbih      = (const float*)d_in[3];
    const float* cbhh      = (const float*)d_in[4];
    const float* word_emb  = (const float*)d_in[5];
    const float* Wih       = (const float*)d_in[6];
    const float* Whh       = (const float*)d_in[7];
    const float* bih       = (const float*)d_in[8];
    const float* bhh       = (const float*)d_in[9];
    const float* W1        = (const float*)d_in[10];
    const float* b1        = (const float*)d_in[11];
    const int*   x         = (const int*)d_in[12];
    const int*   chars     = (const int*)d_in[13];
    const int*   char_lens = (const int*)d_in[14];
    float* out = (float*)d_out;
    (void)in_sizes; (void)n_in; (void)out_size;

    // clear record tags so each (deterministic) replay starts clean
    void* pRec;
    cudaGetSymbolAddress(&pRec, g_hrec);
    cudaMemsetAsync(pRec, 0, sizeof(unsigned long long) * 2 * NH, 0);

    const size_t sm_char = sizeof(float) * (128 * 193 + 32 * 64 + 32 * CH) + sizeof(int) * 32 * LCC;
    const size_t sm_gin  = sizeof(float) * (32 * NK + 128 * 33);
    const size_t sm_log  = sizeof(float) * (64 * 513 + 32 * 512 + 32 * 64);
    cudaFuncSetAttribute(char_lstm_kernel, cudaFuncAttributeMaxDynamicSharedMemorySize, (int)sm_char);
    cudaFuncSetAttribute(word_gin_kernel,  cudaFuncAttributeMaxDynamicSharedMemorySize, (int)sm_gin);
    cudaFuncSetAttribute(logits_kernel,    cudaFuncAttributeMaxDynamicSharedMemorySize, (int)sm_log);

    char_lstm_kernel<<<S_LEN / 32, 256, sm_char>>>(char_emb, cWih, cWhh,
                                                   cbih, cbhh, chars, char_lens);

    dim3 ggrid(S_LEN / 32, NG / 128);
    word_gin_kernel<<<ggrid, 256, sm_gin>>>(word_emb, Wih, bih, bhh, x);

    word_rec_kernel<<<NBW, 256>>>(Whh);

    logits_kernel<<<S_LEN / 32, 256, sm_log>>>(W1, b1, out);
}

// round 4
// speedup vs baseline: 1.4241x; 1.0987x over previous
#include <cuda_runtime.h>
#include <math.h>

#define S_LEN 4096
#define LCC   16
#define CH    128      // char hidden
#define CD    64       // char emb dim
#define CG    512      // 4*CH
#define CK    192      // CD+CH
#define ND    256      // word emb dim
#define NH    512      // word hidden
#define NG    2048     // 4*NH
#define NK    384      // ND+CH
#define NTAG  64
#define NBW   64       // persistent word-rec blocks
#define HPER  8        // NH/NBW

// ---- scratch (__device__ globals; no allocs allowed) ----
__device__ float              g_charH[S_LEN * CH];   // final char-LSTM h
__device__ float              g_gin  [S_LEN * NG];   // word input projection
__device__ float              g_hs   [S_LEN * NH];   // word LSTM hidden states
__device__ unsigned long long g_hrec [2 * NH];       // tagged h records (double buffer)

__device__ __forceinline__ float sigf(float x)  { return 1.0f / (1.0f + __expf(-x)); }
__device__ __forceinline__ float tanhf_fast(float x) { return 2.0f / (1.0f + __expf(-2.0f * x)) - 1.0f; }

// ============================================================================
// Char LSTM: ONE launch, 128 CTAs x 32 words, internal loop over t=0..15.
// ============================================================================
__global__ void __launch_bounds__(256)
char_lstm_kernel(const float* __restrict__ char_emb,
                 const float* __restrict__ cWih,
                 const float* __restrict__ cWhh,
                 const float* __restrict__ cbih,
                 const float* __restrict__ cbhh,
                 const int*   __restrict__ chars,
                 const int*   __restrict__ char_lens)
{
    extern __shared__ float sm[];
    float* wsm  = sm;                       // [128][193]
    float* esm  = wsm + 128 * 193;          // [32][64]
    float* hsm  = esm + 32 * 64;            // [32][128]
    int*   cidx = (int*)(hsm + 32 * CH);    // [32][16]

    const int tid = threadIdx.x;
    const int s0  = blockIdx.x * 32;
    const int tx  = tid & 31, ty = tid >> 5;

    for (int i = tid; i < 32 * LCC; i += 256) cidx[i] = chars[s0 * LCC + i];
    for (int i = tid; i < 32 * CH; i += 256) hsm[i] = 0.0f;

    float c[4][4];
    #pragma unroll
    for (int i = 0; i < 4; i++)
        #pragma unroll
        for (int j = 0; j < 4; j++) c[i][j] = 0.0f;

    int len[4];
    #pragma unroll
    for (int i = 0; i < 4; i++) len[i] = char_lens[s0 + ty + 8 * i];

    float bsum[4][4];
    #pragma unroll
    for (int gc = 0; gc < 4; gc++)
        #pragma unroll
        for (int j = 0; j < 4; j++) {
            int G = gc * 128 + tx + 32 * j;
            bsum[gc][j] = cbih[G] + cbhh[G];
        }
    __syncthreads();

    for (int t = 0; t < LCC; t++) {
        for (int i = tid; i < 32 * CD; i += 256) {
            int w = i >> 6, k = i & 63;
            esm[i] = char_emb[cidx[w * LCC + t] * CD + k];
        }
        __syncthreads();

        float a4[4][4][4];   // [word][hh][gate]
        #pragma unroll
        for (int gc = 0; gc < 4; gc++) {
            for (int i = tid; i < 128 * CK; i += 256) {
                int rr = i / CK, k = i - rr * CK;
                int G = gc * 128 + rr;
                float v = (k < CD) ? cWih[G * CD + k] : cWhh[G * CH + (k - CD)];
                wsm[rr * 193 + k] = v;
            }
            __syncthreads();

            float acc[4][4] = {};
            #pragma unroll 4
            for (int k = 0; k < CD; k++) {
                float b0 = wsm[(tx     ) * 193 + k];
                float b1 = wsm[(tx + 32) * 193 + k];
                float b2 = wsm[(tx + 64) * 193 + k];
                float b3 = wsm[(tx + 96) * 193 + k];
                #pragma unroll
                for (int i = 0; i < 4; i++) {
                    float a = esm[(ty + 8 * i) * CD + k];
                    acc[i][0] = fmaf(a, b0, acc[i][0]);
                    acc[i][1] = fmaf(a, b1, acc[i][1]);
                    acc[i][2] = fmaf(a, b2, acc[i][2]);
                    acc[i][3] = fmaf(a, b3, acc[i][3]);
                }
            }
            #pragma unroll 4
            for (int k = 0; k < CH; k++) {
                float b0 = wsm[(tx     ) * 193 + CD + k];
                float b1 = wsm[(tx + 32) * 193 + CD + k];
                float b2 = wsm[(tx + 64) * 193 + CD + k];
                float b3 = wsm[(tx + 96) * 193 + CD + k];
                #pragma unroll
                for (int i = 0; i < 4; i++) {
                    float a = hsm[(ty + 8 * i) * CH + k];
                    acc[i][0] = fmaf(a, b0, acc[i][0]);
                    acc[i][1] = fmaf(a, b1, acc[i][1]);
                    acc[i][2] = fmaf(a, b2, acc[i][2]);
                    acc[i][3] = fmaf(a, b3, acc[i][3]);
                }
            }
            #pragma unroll
            for (int i = 0; i < 4; i++)
                #pragma unroll
                for (int j = 0; j < 4; j++)
                    a4[i][j][gc] = acc[i][j] + bsum[gc][j];
            __syncthreads();
        }

        #pragma unroll
        for (int i = 0; i < 4; i++) {
            bool m = (t < len[i]);
            int w = ty + 8 * i;
            #pragma unroll
            for (int j = 0; j < 4; j++) {
                float gi = a4[i][j][0], gf = a4[i][j][1];
                float gg = a4[i][j][2], go = a4[i][j][3];
                float cn = sigf(gf) * c[i][j] + sigf(gi) * tanhf_fast(gg);
                float hn = sigf(go) * tanhf_fast(cn);
                if (m) {
                    c[i][j] = cn;
                    hsm[w * CH + tx + 32 * j] = hn;
                }
            }
        }
        __syncthreads();
    }

    for (int i = tid; i < 32 * CH; i += 256)
        g_charH[s0 * CH + i] = hsm[i];
}

// ============================================================================
// Word LSTM input projection
// ============================================================================
__global__ void __launch_bounds__(256)
word_gin_kernel(const float* __restrict__ word_emb,
                const float* __restrict__ Wih,
                const float* __restrict__ bih,
                const float* __restrict__ bhh,
                const int*   __restrict__ x)
{
    extern __shared__ float sm[];
    float* feat = sm;              // [32][NK]
    float* wc   = feat + 32 * NK;  // [128][33]
    const int tid = threadIdx.x;
    const int s0  = blockIdx.x * 32;
    const int g0  = blockIdx.y * 128;

    for (int i = tid; i < 32 * NK; i += 256) {
        int w = i / NK, k = i - w * NK;
        int s = s0 + w;
        float v;
        if (k < ND) v = word_emb[x[s] * ND + k];
        else        v = g_charH[s * CH + (k - ND)];
        feat[w * NK + k] = v;
    }
    __syncthreads();

    const int tx = tid & 31, ty = tid >> 5;
    float acc[4][4] = {};
    for (int kc = 0; kc < NK; kc += 32) {
        for (int i = tid; i < 128 * 32; i += 256) {
            int r = i >> 5, k = i & 31;
            wc[r * 33 + k] = Wih[(g0 + r) * NK + kc + k];
        }
        __syncthreads();
        #pragma unroll 4
        for (int k = 0; k < 32; k++) {
            float b0 = wc[(tx     ) * 33 + k];
            float b1 = wc[(tx + 32) * 33 + k];
            float b2 = wc[(tx + 64) * 33 + k];
            float b3 = wc[(tx + 96) * 33 + k];
            #pragma unroll
            for (int i = 0; i < 4; i++) {
                float a = feat[(ty + 8 * i) * NK + kc + k];
                acc[i][0] = fmaf(a, b0, acc[i][0]);
                acc[i][1] = fmaf(a, b1, acc[i][1]);
                acc[i][2] = fmaf(a, b2, acc[i][2]);
                acc[i][3] = fmaf(a, b3, acc[i][3]);
            }
        }
        __syncthreads();
    }
    #pragma unroll
    for (int j = 0; j < 4; j++) {
        int g = g0 + tx + 32 * j;
        float bsum = bih[g] + bhh[g];
        #pragma unroll
        for (int i = 0; i < 4; i++)
            g_gin[(s0 + ty + 8 * i) * NG + g] = acc[i][j] + bsum;
    }
}

// ============================================================================
// Word LSTM recurrence v2: per-warp wavefront.
//  - warp s polls ONLY its own 64 h records (self-produced SMEM range) ->
//    no block barrier before the FMAs, warps decouple.
//  - part[] double-buffered; warps 1-7 post results via bar.arrive (named,
//    parity-alternated) and immediately start step t+1; warp 0 bar.sync's,
//    reduces, applies activations ACROSS 32 lanes (one sig/tanh each),
//    shfl-gathers, updates c on lanes 0-7, publishes tagged records.
// ============================================================================
__global__ void __launch_bounds__(256)
word_rec_kernel(const float* __restrict__ Whh)
{
    __shared__ float hsm[NH];
    __shared__ float part[2][256];
    const int tid  = threadIdx.x;
    const int lane = tid & 31;
    const int warp = tid >> 5;
    const int G    = (lane >> 3) * NH + blockIdx.x * HPER + (lane & 7);

    float W[64];
    #pragma unroll
    for (int j = 0; j < 64; j++) W[j] = Whh[G * NH + warp * 64 + j];

    float c = 0.0f;
    const int r0 = 2 * tid, r1 = 2 * tid + 1;

    for (int t = 0; t < S_LEN; t++) {
        float ginv = (warp == 0) ? __ldg(&g_gin[t * NG + G]) : 0.0f;

        if (t > 0) {
            const unsigned tag = (unsigned)t;  // h(t-1) carries tag t
            const volatile unsigned long long* rec = g_hrec + ((t - 1) & 1) * NH;
            unsigned long long v0 = rec[r0];
            unsigned long long v1 = rec[r1];
            while ((unsigned)(v0 >> 32) != tag) v0 = rec[r0];
            while ((unsigned)(v1 >> 32) != tag) v1 = rec[r1];
            hsm[r0] = __uint_as_float((unsigned)v0);
            hsm[r1] = __uint_as_float((unsigned)v1);
        } else {
            hsm[r0] = 0.0f;
            hsm[r1] = 0.0f;
        }
        __syncwarp();   // warp s reads only hsm[64s..64s+63] == its own writes

        // 4-accumulator dot product over this warp's k-slice
        const float* hp = hsm + warp * 64;
        float a0 = 0.f, a1 = 0.f, a2 = 0.f, a3 = 0.f;
        #pragma unroll
        for (int j = 0; j < 16; j++) {
            a0 = fmaf(W[4 * j    ], hp[4 * j    ], a0);
            a1 = fmaf(W[4 * j + 1], hp[4 * j + 1], a1);
            a2 = fmaf(W[4 * j + 2], hp[4 * j + 2], a2);
            a3 = fmaf(W[4 * j + 3], hp[4 * j + 3], a3);
        }
        part[t & 1][warp * 32 + lane] = (a0 + a1) + (a2 + a3);

        const int barid = 1 + (t & 1);
        if (warp != 0) {
            asm volatile("bar.arrive %0, 256;" :: "r"(barid));
            // free to run ahead into step t+1 (poll will gate on h(t))
        } else {
            asm volatile("bar.sync %0, 256;" :: "r"(barid));
            const float* pp = part[t & 1];
            float g = ginv;
            #pragma unroll
            for (int sb = 0; sb < 8; sb++) g += pp[sb * 32 + lane];
            // lanes 0-7: i | 8-15: f | 16-23: g(tanh) | 24-31: o
            float act = (lane >= 16 && lane < 24) ? tanhf_fast(g) : sigf(g);
            float i_ = __shfl_sync(0xffffffffu, act, (lane & 7));
            float f_ = __shfl_sync(0xffffffffu, act, 8 + (lane & 7));
            float g_ = __shfl_sync(0xffffffffu, act, 16 + (lane & 7));
            float o_ = __shfl_sync(0xffffffffu, act, 24 + (lane & 7));
            if (lane < 8) {
                float cn = f_ * c + i_ * g_;
                c = cn;
                float hn = o_ * tanhf_fast(cn);
                int hidx = blockIdx.x * HPER + lane;
                g_hs[t * NH + hidx] = hn;
                unsigned long long pk =
                    ((unsigned long long)(unsigned)(t + 1) << 32) | __float_as_uint(hn);
                *(volatile unsigned long long*)(g_hrec + (t & 1) * NH + hidx) = pk;
            }
        }
    }
}

// ============================================================================
// Logits + log_softmax
// ============================================================================
__global__ void __launch_bounds__(256)
logits_kernel(const float* __restrict__ W1,
              const float* __restrict__ b1,
              float* __restrict__ out)
{
    extern __shared__ float sm[];
    float* w1s = sm;                 // [64][513]
    float* hsm = w1s + 64 * 513;     // [32][512]
    float* lsm = hsm + 32 * 512;     // [32][64]
    const int tid = threadIdx.x;
    const int s0  = blockIdx.x * 32;

    for (int i = tid; i < 64 * 512; i += 256) {
        int rr = i >> 9, k = i & 511;
        w1s[rr * 513 + k] = W1[i];
    }
    for (int i = tid; i < 32 * 512; i += 256)
        hsm[i] = g_hs[s0 * 512 + i];
    __syncthreads();

    const int tg = tid & 63, wg = tid >> 6;
    float acc[8];
    #pragma unroll
    for (int i = 0; i < 8; i++) acc[i] = b1[tg];
    #pragma unroll 4
    for (int k = 0; k < 512; k++) {
        float b = w1s[tg * 513 + k];
        #pragma unroll
        for (int i = 0; i < 8; i++)
            acc[i] = fmaf(hsm[(wg + 4 * i) * 512 + k], b, acc[i]);
    }
    #pragma unroll
    for (int i = 0; i < 8; i++)
        lsm[(wg + 4 * i) * 64 + tg] = acc[i];
    __syncthreads();

    const int lane = tid & 31, wrp = tid >> 5;
    for (int wi = 0; wi < 4; wi++) {
        int w = wrp * 4 + wi;
        float v0 = lsm[w * 64 + lane];
        float v1 = lsm[w * 64 + 32 + lane];
        float m = fmaxf(v0, v1);
        #pragma unroll
        for (int o = 16; o > 0; o >>= 1) m = fmaxf(m, __shfl_xor_sync(0xffffffffu, m, o));
        float se = expf(v0 - m) + expf(v1 - m);
        #pragma unroll
        for (int o = 16; o > 0; o >>= 1) se += __shfl_xor_sync(0xffffffffu, se, o);
        float ls = m + logf(se);
        out[(s0 + w) * 64 + lane]      = v0 - ls;
        out[(s0 + w) * 64 + 32 + lane] = v1 - ls;
    }
}

// ============================================================================
extern "C" void kernel_launch(void* const* d_in, const int* in_sizes, int n_in,
                              void* d_out, int out_size)
{
    const float* char_emb  = (const float*)d_in[0];
    const float* cWih      = (const float*)d_in[1];
    const float* cWhh      = (const float*)d_in[2];
    const float* cbih      = (const float*)d_in[3];
    const float* cbhh      = (const float*)d_in[4];
    const float* word_emb  = (const float*)d_in[5];
    const float* Wih       = (const float*)d_in[6];
    const float* Whh       = (const float*)d_in[7];
    const float* bih       = (const float*)d_in[8];
    const float* bhh       = (const float*)d_in[9];
    const float* W1        = (const float*)d_in[10];
    const float* b1        = (const float*)d_in[11];
    const int*   x         = (const int*)d_in[12];
    const int*   chars     = (const int*)d_in[13];
    const int*   char_lens = (const int*)d_in[14];
    float* out = (float*)d_out;
    (void)in_sizes; (void)n_in; (void)out_size;

    void* pRec;
    cudaGetSymbolAddress(&pRec, g_hrec);
    cudaMemsetAsync(pRec, 0, sizeof(unsigned long long) * 2 * NH, 0);

    const size_t sm_char = sizeof(float) * (128 * 193 + 32 * 64 + 32 * CH) + sizeof(int) * 32 * LCC;
    const size_t sm_gin  = sizeof(float) * (32 * NK + 128 * 33);
    const size_t sm_log  = sizeof(float) * (64 * 513 + 32 * 512 + 32 * 64);
    cudaFuncSetAttribute(char_lstm_kernel, cudaFuncAttributeMaxDynamicSharedMemorySize, (int)sm_char);
    cudaFuncSetAttribute(word_gin_kernel,  cudaFuncAttributeMaxDynamicSharedMemorySize, (int)sm_gin);
    cudaFuncSetAttribute(logits_kernel,    cudaFuncAttributeMaxDynamicSharedMemorySize, (int)sm_log);

    char_lstm_kernel<<<S_LEN / 32, 256, sm_char>>>(char_emb, cWih, cWhh,
                                                   cbih, cbhh, chars, char_lens);

    dim3 ggrid(S_LEN / 32, NG / 128);
    word_gin_kernel<<<ggrid, 256, sm_gin>>>(word_emb, Wih, bih, bhh, x);

    word_rec_kernel<<<NBW, 256>>>(Whh);

    logits_kernel<<<S_LEN / 32, 256, sm_log>>>(W1, b1, out);
}

// round 5
// speedup vs baseline: 1.6110x; 1.1313x over previous
#include <cuda_runtime.h>
#include <math.h>

#define S_LEN 4096
#define LCC   16
#define CH    128      // char hidden
#define CD    64       // char emb dim
#define CG    512      // 4*CH
#define CK    192      // CD+CH
#define ND    256      // word emb dim
#define NH    512      // word hidden
#define NG    2048     // 4*NH
#define NK    384      // ND+CH
#define NTAG  64
#define NBW   64       // persistent word-rec blocks
#define HPER  8        // NH/NBW
#define NREP  4        // record replicas (contention spreading)

// ---- scratch (__device__ globals; no allocs allowed) ----
__device__ float              g_charH[S_LEN * CH];
__device__ float              g_gin  [S_LEN * NG];
__device__ float              g_hs   [S_LEN * NH];
// tagged h records: [replica][parity][NH], 16B-aligned for v2.u64 polling
__device__ __align__(16) unsigned long long g_hrec[NREP * 2 * NH];

__device__ __forceinline__ float sigf(float x)  { return 1.0f / (1.0f + __expf(-x)); }
__device__ __forceinline__ float tanhf_fast(float x) { return 2.0f / (1.0f + __expf(-2.0f * x)) - 1.0f; }

__device__ __forceinline__ void ldv2_volatile(const unsigned long long* p,
                                              unsigned long long& a,
                                              unsigned long long& b)
{
    asm volatile("ld.volatile.global.v2.u64 {%0,%1},[%2];"
                 : "=l"(a), "=l"(b) : "l"(p) : "memory");
}

// ============================================================================
// Char LSTM: ONE launch, 128 CTAs x 32 words, internal loop over t=0..15.
// ============================================================================
__global__ void __launch_bounds__(256)
char_lstm_kernel(const float* __restrict__ char_emb,
                 const float* __restrict__ cWih,
                 const float* __restrict__ cWhh,
                 const float* __restrict__ cbih,
                 const float* __restrict__ cbhh,
                 const int*   __restrict__ chars,
                 const int*   __restrict__ char_lens)
{
    extern __shared__ float sm[];
    float* wsm  = sm;                       // [128][193]
    float* esm  = wsm + 128 * 193;          // [32][64]
    float* hsm  = esm + 32 * 64;            // [32][128]
    int*   cidx = (int*)(hsm + 32 * CH);    // [32][16]

    const int tid = threadIdx.x;
    const int s0  = blockIdx.x * 32;
    const int tx  = tid & 31, ty = tid >> 5;

    for (int i = tid; i < 32 * LCC; i += 256) cidx[i] = chars[s0 * LCC + i];
    for (int i = tid; i < 32 * CH; i += 256) hsm[i] = 0.0f;

    float c[4][4];
    #pragma unroll
    for (int i = 0; i < 4; i++)
        #pragma unroll
        for (int j = 0; j < 4; j++) c[i][j] = 0.0f;

    int len[4];
    #pragma unroll
    for (int i = 0; i < 4; i++) len[i] = char_lens[s0 + ty + 8 * i];

    float bsum[4][4];
    #pragma unroll
    for (int gc = 0; gc < 4; gc++)
        #pragma unroll
        for (int j = 0; j < 4; j++) {
            int G = gc * 128 + tx + 32 * j;
            bsum[gc][j] = cbih[G] + cbhh[G];
        }
    __syncthreads();

    for (int t = 0; t < LCC; t++) {
        for (int i = tid; i < 32 * CD; i += 256) {
            int w = i >> 6, k = i & 63;
            esm[i] = char_emb[cidx[w * LCC + t] * CD + k];
        }
        __syncthreads();

        float a4[4][4][4];
        #pragma unroll
        for (int gc = 0; gc < 4; gc++) {
            for (int i = tid; i < 128 * CK; i += 256) {
                int rr = i / CK, k = i - rr * CK;
                int G = gc * 128 + rr;
                float v = (k < CD) ? cWih[G * CD + k] : cWhh[G * CH + (k - CD)];
                wsm[rr * 193 + k] = v;
            }
            __syncthreads();

            float acc[4][4] = {};
            #pragma unroll 4
            for (int k = 0; k < CD; k++) {
                float b0 = wsm[(tx     ) * 193 + k];
                float b1 = wsm[(tx + 32) * 193 + k];
                float b2 = wsm[(tx + 64) * 193 + k];
                float b3 = wsm[(tx + 96) * 193 + k];
                #pragma unroll
                for (int i = 0; i < 4; i++) {
                    float a = esm[(ty + 8 * i) * CD + k];
                    acc[i][0] = fmaf(a, b0, acc[i][0]);
                    acc[i][1] = fmaf(a, b1, acc[i][1]);
                    acc[i][2] = fmaf(a, b2, acc[i][2]);
                    acc[i][3] = fmaf(a, b3, acc[i][3]);
                }
            }
            #pragma unroll 4
            for (int k = 0; k < CH; k++) {
                float b0 = wsm[(tx     ) * 193 + CD + k];
                float b1 = wsm[(tx + 32) * 193 + CD + k];
                float b2 = wsm[(tx + 64) * 193 + CD + k];
                float b3 = wsm[(tx + 96) * 193 + CD + k];
                #pragma unroll
                for (int i = 0; i < 4; i++) {
                    float a = hsm[(ty + 8 * i) * CH + k];
                    acc[i][0] = fmaf(a, b0, acc[i][0]);
                    acc[i][1] = fmaf(a, b1, acc[i][1]);
                    acc[i][2] = fmaf(a, b2, acc[i][2]);
                    acc[i][3] = fmaf(a, b3, acc[i][3]);
                }
            }
            #pragma unroll
            for (int i = 0; i < 4; i++)
                #pragma unroll
                for (int j = 0; j < 4; j++)
                    a4[i][j][gc] = acc[i][j] + bsum[gc][j];
            __syncthreads();
        }

        #pragma unroll
        for (int i = 0; i < 4; i++) {
            bool m = (t < len[i]);
            int w = ty + 8 * i;
            #pragma unroll
            for (int j = 0; j < 4; j++) {
                float gi = a4[i][j][0], gf = a4[i][j][1];
                float gg = a4[i][j][2], go = a4[i][j][3];
                float cn = sigf(gf) * c[i][j] + sigf(gi) * tanhf_fast(gg);
                float hn = sigf(go) * tanhf_fast(cn);
                if (m) {
                    c[i][j] = cn;
                    hsm[w * CH + tx + 32 * j] = hn;
                }
            }
        }
        __syncthreads();
    }

    for (int i = tid; i < 32 * CH; i += 256)
        g_charH[s0 * CH + i] = hsm[i];
}

// ============================================================================
// Word LSTM input projection
// ============================================================================
__global__ void __launch_bounds__(256)
word_gin_kernel(const float* __restrict__ word_emb,
                const float* __restrict__ Wih,
                const float* __restrict__ bih,
                const float* __restrict__ bhh,
                const int*   __restrict__ x)
{
    extern __shared__ float sm[];
    float* feat = sm;              // [32][NK]
    float* wc   = feat + 32 * NK;  // [128][33]
    const int tid = threadIdx.x;
    const int s0  = blockIdx.x * 32;
    const int g0  = blockIdx.y * 128;

    for (int i = tid; i < 32 * NK; i += 256) {
        int w = i / NK, k = i - w * NK;
        int s = s0 + w;
        float v;
        if (k < ND) v = word_emb[x[s] * ND + k];
        else        v = g_charH[s * CH + (k - ND)];
        feat[w * NK + k] = v;
    }
    __syncthreads();

    const int tx = tid & 31, ty = tid >> 5;
    float acc[4][4] = {};
    for (int kc = 0; kc < NK; kc += 32) {
        for (int i = tid; i < 128 * 32; i += 256) {
            int r = i >> 5, k = i & 31;
            wc[r * 33 + k] = Wih[(g0 + r) * NK + kc + k];
        }
        __syncthreads();
        #pragma unroll 4
        for (int k = 0; k < 32; k++) {
            float b0 = wc[(tx     ) * 33 + k];
            float b1 = wc[(tx + 32) * 33 + k];
            float b2 = wc[(tx + 64) * 33 + k];
            float b3 = wc[(tx + 96) * 33 + k];
            #pragma unroll
            for (int i = 0; i < 4; i++) {
                float a = feat[(ty + 8 * i) * NK + kc + k];
                acc[i][0] = fmaf(a, b0, acc[i][0]);
                acc[i][1] = fmaf(a, b1, acc[i][1]);
                acc[i][2] = fmaf(a, b2, acc[i][2]);
                acc[i][3] = fmaf(a, b3, acc[i][3]);
            }
        }
        __syncthreads();
    }
    #pragma unroll
    for (int j = 0; j < 4; j++) {
        int g = g0 + tx + 32 * j;
        float bsum = bih[g] + bhh[g];
        #pragma unroll
        for (int i = 0; i < 4; i++)
            g_gin[(s0 + ty + 8 * i) * NG + g] = acc[i][j] + bsum;
    }
}

// ============================================================================
// Word LSTM recurrence v3: per-warp wavefront + replicated records.
//  - producers publish each h record to NREP replica buffers; consumer CTA
//    polls only replica (blockIdx & 3) -> 4x fewer readers per L2 line.
//  - each thread polls its 2 adjacent records with ONE 16B v2.u64 load.
//  - record publish happens BEFORE the g_hs side store.
// ============================================================================
__global__ void __launch_bounds__(256)
word_rec_kernel(const float* __restrict__ Whh)
{
    __shared__ float hsm[NH];
    __shared__ float part[2][256];
    const int tid  = threadIdx.x;
    const int lane = tid & 31;
    const int warp = tid >> 5;
    const int G    = (lane >> 3) * NH + blockIdx.x * HPER + (lane & 7);
    const int ridx = blockIdx.x & (NREP - 1);

    float W[64];
    #pragma unroll
    for (int j = 0; j < 64; j++) W[j] = Whh[G * NH + warp * 64 + j];

    float c = 0.0f;
    const int r0 = 2 * tid;

    for (int t = 0; t < S_LEN; t++) {
        float ginv = (warp == 0) ? __ldg(&g_gin[t * NG + G]) : 0.0f;

        if (t > 0) {
            const unsigned tag = (unsigned)t;  // h(t-1) carries tag t
            const unsigned long long* rec =
                g_hrec + (ridx * 2 + ((t - 1) & 1)) * NH + r0;
            unsigned long long v0, v1;
            ldv2_volatile(rec, v0, v1);
            while ((unsigned)(v0 >> 32) != tag || (unsigned)(v1 >> 32) != tag)
                ldv2_volatile(rec, v0, v1);
            hsm[r0]     = __uint_as_float((unsigned)v0);
            hsm[r0 + 1] = __uint_as_float((unsigned)v1);
        } else {
            hsm[r0]     = 0.0f;
            hsm[r0 + 1] = 0.0f;
        }
        __syncwarp();   // warp s reads only hsm[64s..64s+63] == its own writes

        // dot product over this warp's k-slice (float4 SMEM reads, 4 accs)
        const float4* hp4 = (const float4*)(hsm + warp * 64);
        float a0 = 0.f, a1 = 0.f, a2 = 0.f, a3 = 0.f;
        #pragma unroll
        for (int j = 0; j < 16; j++) {
            float4 hv = hp4[j];
            a0 = fmaf(W[4 * j    ], hv.x, a0);
            a1 = fmaf(W[4 * j + 1], hv.y, a1);
            a2 = fmaf(W[4 * j + 2], hv.z, a2);
            a3 = fmaf(W[4 * j + 3], hv.w, a3);
        }
        part[t & 1][warp * 32 + lane] = (a0 + a1) + (a2 + a3);

        const int barid = 1 + (t & 1);
        if (warp != 0) {
            asm volatile("bar.arrive %0, 256;" :: "r"(barid));
            // run ahead into step t+1 (poll gates on h(t))
        } else {
            asm volatile("bar.sync %0, 256;" :: "r"(barid));
            const float* pp = part[t & 1];
            float g = ginv;
            #pragma unroll
            for (int sb = 0; sb < 8; sb++) g += pp[sb * 32 + lane];
            // lanes 0-7: i | 8-15: f | 16-23: g(tanh) | 24-31: o
            float act = (lane >= 16 && lane < 24) ? tanhf_fast(g) : sigf(g);
            float i_ = __shfl_sync(0xffffffffu, act, (lane & 7));
            float f_ = __shfl_sync(0xffffffffu, act, 8 + (lane & 7));
            float g_ = __shfl_sync(0xffffffffu, act, 16 + (lane & 7));
            float o_ = __shfl_sync(0xffffffffu, act, 24 + (lane & 7));
            if (lane < 8) {
                float cn = f_ * c + i_ * g_;
                c = cn;
                float hn = o_ * tanhf_fast(cn);
                int hidx = blockIdx.x * HPER + lane;
                unsigned long long pk =
                    ((unsigned long long)(unsigned)(t + 1) << 32) | __float_as_uint(hn);
                // publish to all replicas FIRST (critical path), then g_hs
                #pragma unroll
                for (int rp = 0; rp < NREP; rp++)
                    *(volatile unsigned long long*)
                        (g_hrec + (rp * 2 + (t & 1)) * NH + hidx) = pk;
                g_hs[t * NH + hidx] = hn;
            }
        }
    }
}

// ============================================================================
// Logits + log_softmax
// ============================================================================
__global__ void __launch_bounds__(256)
logits_kernel(const float* __restrict__ W1,
              const float* __restrict__ b1,
              float* __restrict__ out)
{
    extern __shared__ float sm[];
    float* w1s = sm;                 // [64][513]
    float* hsm = w1s + 64 * 513;     // [32][512]
    float* lsm = hsm + 32 * 512;     // [32][64]
    const int tid = threadIdx.x;
    const int s0  = blockIdx.x * 32;

    for (int i = tid; i < 64 * 512; i += 256) {
        int rr = i >> 9, k = i & 511;
        w1s[rr * 513 + k] = W1[i];
    }
    for (int i = tid; i < 32 * 512; i += 256)
        hsm[i] = g_hs[s0 * 512 + i];
    __syncthreads();

    const int tg = tid & 63, wg = tid >> 6;
    float acc[8];
    #pragma unroll
    for (int i = 0; i < 8; i++) acc[i] = b1[tg];
    #pragma unroll 4
    for (int k = 0; k < 512; k++) {
        float b = w1s[tg * 513 + k];
        #pragma unroll
        for (int i = 0; i < 8; i++)
            acc[i] = fmaf(hsm[(wg + 4 * i) * 512 + k], b, acc[i]);
    }
    #pragma unroll
    for (int i = 0; i < 8; i++)
        lsm[(wg + 4 * i) * 64 + tg] = acc[i];
    __syncthreads();

    const int lane = tid & 31, wrp = tid >> 5;
    for (int wi = 0; wi < 4; wi++) {
        int w = wrp * 4 + wi;
        float v0 = lsm[w * 64 + lane];
        float v1 = lsm[w * 64 + 32 + lane];
        float m = fmaxf(v0, v1);
        #pragma unroll
        for (int o = 16; o > 0; o >>= 1) m = fmaxf(m, __shfl_xor_sync(0xffffffffu, m, o));
        float se = expf(v0 - m) + expf(v1 - m);
        #pragma unroll
        for (int o = 16; o > 0; o >>= 1) se += __shfl_xor_sync(0xffffffffu, se, o);
        float ls = m + logf(se);
        out[(s0 + w) * 64 + lane]      = v0 - ls;
        out[(s0 + w) * 64 + 32 + lane] = v1 - ls;
    }
}

// ============================================================================
extern "C" void kernel_launch(void* const* d_in, const int* in_sizes, int n_in,
                              void* d_out, int out_size)
{
    const float* char_emb  = (const float*)d_in[0];
    const float* cWih      = (const float*)d_in[1];
    const float* cWhh      = (const float*)d_in[2];
    const float* cbih      = (const float*)d_in[3];
    const float* cbhh      = (const float*)d_in[4];
    const float* word_emb  = (const float*)d_in[5];
    const float* Wih       = (const float*)d_in[6];
    const float* Whh       = (const float*)d_in[7];
    const float* bih       = (const float*)d_in[8];
    const float* bhh       = (const float*)d_in[9];
    const float* W1        = (const float*)d_in[10];
    const float* b1        = (const float*)d_in[11];
    const int*   x         = (const int*)d_in[12];
    const int*   chars     = (const int*)d_in[13];
    const int*   char_lens = (const int*)d_in[14];
    float* out = (float*)d_out;
    (void)in_sizes; (void)n_in; (void)out_size;

    void* pRec;
    cudaGetSymbolAddress(&pRec, g_hrec);
    cudaMemsetAsync(pRec, 0, sizeof(unsigned long long) * NREP * 2 * NH, 0);

    const size_t sm_char = sizeof(float) * (128 * 193 + 32 * 64 + 32 * CH) + sizeof(int) * 32 * LCC;
    const size_t sm_gin  = sizeof(float) * (32 * NK + 128 * 33);
    const size_t sm_log  = sizeof(float) * (64 * 513 + 32 * 512 + 32 * 64);
    cudaFuncSetAttribute(char_lstm_kernel, cudaFuncAttributeMaxDynamicSharedMemorySize, (int)sm_char);
    cudaFuncSetAttribute(word_gin_kernel,  cudaFuncAttributeMaxDynamicSharedMemorySize, (int)sm_gin);
    cudaFuncSetAttribute(logits_kernel,    cudaFuncAttributeMaxDynamicSharedMemorySize, (int)sm_log);

    char_lstm_kernel<<<S_LEN / 32, 256, sm_char>>>(char_emb, cWih, cWhh,
                                                   cbih, cbhh, chars, char_lens);

    dim3 ggrid(S_LEN / 32, NG / 128);
    word_gin_kernel<<<ggrid, 256, sm_gin>>>(word_emb, Wih, bih, bhh, x);

    word_rec_kernel<<<NBW, 256>>>(Whh);

    logits_kernel<<<S_LEN / 32, 256, sm_log>>>(W1, b1, out);
}